// round 1
// baseline (speedup 1.0000x reference)
#include <cuda_runtime.h>
#include <cuda_bf16.h>

// Problem constants (fixed shapes from reference)
#define B_      64
#define K_      5
#define NPIX    102400          // 320*320
#define CHUNK   4096
#define NCHUNK  (NPIX / CHUNK)  // 25
#define THREADS 256
#define EPSV    1e-6

// Scratch: __device__ globals (no allocation allowed)
// Per-block partials: [5 sums per k for 5 k's] + [target sum] = 26 values
__device__ float  g_part[B_ * NCHUNK][26];
__device__ double g_bsum[B_];

// Per-element accumulation:
//   sigma    = sigmoid(x)            (via e = exp(-|x|), r = 1/(1+e))
//   softplus = max(x,0) + log(1+e)   (== max(x,0) - x*t + log1p(exp(-|x|)) + x*t ... BCE pieces)
__device__ __forceinline__ void accum_one(float x, float t,
                                          float& A, float& Bv, float& C,
                                          float& D, float& E) {
    float ax = fabsf(x);
    float e  = __expf(-ax);                     // EX2 (+1 mul), e in (0,1]
    float r  = __fdividef(1.0f, 1.0f + e);      // RCP (+1 mul)
    float sg = (x >= 0.0f) ? r : (1.0f - r);    // sigmoid(x)
    float sp = fmaxf(x, 0.0f) + __logf(1.0f + e); // softplus(x), LG2 (+1 mul)
    A += sg;
    Bv = fmaf(sg, t, Bv);
    C += sp;
    D += x;
    E  = fmaf(x, t, E);
}

__global__ __launch_bounds__(THREADS)
void pass1_kernel(const float* __restrict__ slot, const float* __restrict__ tgt) {
    const int blk = blockIdx.x;           // b * NCHUNK + c
    const int b   = blk / NCHUNK;
    const int c   = blk % NCHUNK;
    const int tid = threadIdx.x;

    // Load this block's target chunk once (kept in registers across all K slots)
    const float4* tp = reinterpret_cast<const float4*>(tgt + (size_t)b * NPIX + (size_t)c * CHUNK);
    float4 tv[4];
#pragma unroll
    for (int j = 0; j < 4; j++) tv[j] = tp[tid + j * THREADS];

    float accF = 0.0f;
#pragma unroll
    for (int j = 0; j < 4; j++) accF += (tv[j].x + tv[j].y) + (tv[j].z + tv[j].w);

    float aA[K_], aB[K_], aC[K_], aD[K_], aE[K_];
#pragma unroll
    for (int k = 0; k < K_; k++) { aA[k] = aB[k] = aC[k] = aD[k] = aE[k] = 0.0f; }

#pragma unroll
    for (int k = 0; k < K_; k++) {
        const float4* sp = reinterpret_cast<const float4*>(
            slot + ((size_t)(b * K_ + k)) * NPIX + (size_t)c * CHUNK);
#pragma unroll
        for (int j = 0; j < 4; j++) {
            float4 sv = sp[tid + j * THREADS];
            accum_one(sv.x, tv[j].x, aA[k], aB[k], aC[k], aD[k], aE[k]);
            accum_one(sv.y, tv[j].y, aA[k], aB[k], aC[k], aD[k], aE[k]);
            accum_one(sv.z, tv[j].z, aA[k], aB[k], aC[k], aD[k], aE[k]);
            accum_one(sv.w, tv[j].w, aA[k], aB[k], aC[k], aD[k], aE[k]);
        }
    }

    // Pack the 26 per-thread sums and do a single block reduction phase
    float vals[26];
#pragma unroll
    for (int k = 0; k < K_; k++) {
        vals[k * 5 + 0] = aA[k];
        vals[k * 5 + 1] = aB[k];
        vals[k * 5 + 2] = aC[k];
        vals[k * 5 + 3] = aD[k];
        vals[k * 5 + 4] = aE[k];
    }
    vals[25] = accF;

    __shared__ float sh[8][26];
    const int lane = tid & 31;
    const int w    = tid >> 5;
#pragma unroll
    for (int v = 0; v < 26; v++) {
        float x = vals[v];
#pragma unroll
        for (int o = 16; o > 0; o >>= 1) x += __shfl_down_sync(0xffffffffu, x, o);
        if (lane == 0) sh[w][v] = x;
    }
    __syncthreads();
    if (tid < 26) {
        float s = 0.0f;
#pragma unroll
        for (int ww = 0; ww < 8; ww++) s += sh[ww][tid];
        g_part[blk][tid] = s;
    }
}

// One block per batch image: reduce chunk partials, do the collapsed Hungarian
// argmin (which slot gets the fg column), and the per-b BCE sum.
__global__ void pass2_kernel() {
    const int b = blockIdx.x;
    const int t = threadIdx.x;  // 32 threads (1 warp)
    __shared__ double sh[26];
    if (t < 26) {
        double s = 0.0;
        for (int c = 0; c < NCHUNK; c++) s += (double)g_part[b * NCHUNK + c][t];
        sh[t] = s;
    }
    __syncwarp();
    if (t == 0) {
        const double F   = sh[25];               // sum of target (fg area)
        const double Tbg = (double)NPIX - F;     // bg area

        int    k0   = 0;
        double best = 1e300;
        double Cs = 0.0, Ds[K_], Es[K_];
        for (int k = 0; k < K_; k++) {
            const double A  = sh[k * 5 + 0];     // sum sigma
            const double Bv = sh[k * 5 + 1];     // sum sigma * t
            Cs   += sh[k * 5 + 2];               // sum softplus
            Ds[k] = sh[k * 5 + 3];               // sum x
            Es[k] = sh[k * 5 + 4];               // sum x * t
            const double Ifg = Bv;
            const double Ibg = A - Bv;
            const double cf  = 1.0 - Ifg / (A + F   - Ifg + EPSV);
            const double cb  = 1.0 - Ibg / (A + Tbg - Ibg + EPSV);
            const double d   = cf - cb;          // marginal benefit of giving k the fg column
            if (d < best) { best = d; k0 = k; }  // strict '<' => first (smallest k) on ties,
                                                 // matching lexicographic-first in PERMS
        }
        double sx = 0.0;
        for (int k = 0; k < K_; k++) sx += (k == k0) ? Es[k] : (Ds[k] - Es[k]);
        g_bsum[b] = Cs - sx;                     // sum of BCE over this image's K*N elements
    }
}

__global__ void pass3_kernel(float* __restrict__ out) {
    if (threadIdx.x == 0) {
        double s = 0.0;
        for (int b = 0; b < B_; b++) s += g_bsum[b];
        out[0] = (float)(s / ((double)B_ * (double)K_ * (double)NPIX));
    }
}

extern "C" void kernel_launch(void* const* d_in, const int* in_sizes, int n_in,
                              void* d_out, int out_size) {
    // d_in[0] = fg_logits (unused by the reference math)
    const float* slot = (const float*)d_in[1];   // (B, K, H, W)
    const float* tgt  = (const float*)d_in[2];   // (B, 1, H, W)
    float* out = (float*)d_out;

    pass1_kernel<<<B_ * NCHUNK, THREADS>>>(slot, tgt);
    pass2_kernel<<<B_, 32>>>();
    pass3_kernel<<<1, 32>>>(out);
}